// round 3
// baseline (speedup 1.0000x reference)
#include <cuda_runtime.h>
#include <cuda_bf16.h>
#include <math.h>

// Problem constants (fixed by the dataset)
#define BMAX 1024
#define EMAX 32768
#define CC   64
#define DD   64

// Scratch (static device globals — no allocation allowed)
__device__ long long g_offsets[BMAX + 1];
__device__ int       g_edge_user[EMAX];
__device__ float     g_M1t[DD * DD];     // [j][d] : self part of Wb^T Wf
__device__ float     g_M2t[DD * DD];     // [j][d] : friend part
__device__ float     g_vself[BMAX * DD];
__device__ float     g_v[(size_t)EMAX * DD];

// ---------------------------------------------------------------------------
// Kernel 1: dtype-robust prefix-scan of counts, fill edge->user map.
// counts may arrive as int64 (reference dtype) or int32 (harness cast).
// Detect by which interpretation sums to exactly E.
// ---------------------------------------------------------------------------
__global__ void setup_kernel(const void* __restrict__ counts_raw, int B, int E) {
    __shared__ long long s[BMAX];
    __shared__ int use64;
    int t = threadIdx.x;

    const long long* c64 = (const long long*)counts_raw;
    const int*       c32 = (const int*)counts_raw;

    // --- pass 1: sum of the int64 interpretation ---
    long long v64 = (t < B) ? c64[t] : 0;
    s[t] = v64;
    __syncthreads();
    for (int o = BMAX >> 1; o > 0; o >>= 1) {
        if (t < o) s[t] += s[t + o];
        __syncthreads();
    }
    if (t == 0) use64 = (s[0] == (long long)E) ? 1 : 0;
    __syncthreads();
    int u64 = use64;
    __syncthreads();   // s[] reuse barrier

    // --- selected count for this thread ---
    long long c = 0;
    if (t < B) c = u64 ? c64[t] : (long long)c32[t];
    // clamp to sane range so a surprise can't turn into OOB writes
    if (c < 0) c = 0;
    if (c > (long long)EMAX) c = EMAX;

    s[t] = c;
    __syncthreads();
    // Hillis-Steele inclusive scan over 1024
    for (int o = 1; o < BMAX; o <<= 1) {
        long long add = (t >= o) ? s[t - o] : 0;
        __syncthreads();
        s[t] += add;
        __syncthreads();
    }
    if (t == 0) g_offsets[0] = 0;
    if (t < B) g_offsets[t + 1] = s[t];
    long long off = s[t] - c;   // exclusive
    if (t < B) {
        for (long long i = 0; i < c; i++) {
            long long idx = off + i;
            if (idx >= 0 && idx < (long long)EMAX) g_edge_user[idx] = t;
        }
    }
}

// ---------------------------------------------------------------------------
// Kernel 2: M1t[j][d] = sum_f Wb[f][d] * Wf[f][j]
//           M2t[j][d] = sum_f Wb[f][d] * Wf[f][64+j]
// ---------------------------------------------------------------------------
__global__ void mfold_kernel(const float* __restrict__ Wf,
                             const float* __restrict__ Wb) {
    int idx = blockIdx.x * blockDim.x + threadIdx.x;  // 8192 threads
    if (idx >= 2 * DD * DD) return;
    int d = idx & 63;
    int j = (idx >> 6) & 63;
    int which = idx >> 12;   // 0: M1, 1: M2
    float acc = 0.f;
#pragma unroll 8
    for (int f = 0; f < 64; f++)
        acc = fmaf(Wb[f * 64 + d], Wf[f * 128 + which * 64 + j], acc);
    if (which) g_M2t[j * 64 + d] = acc;
    else       g_M1t[j * 64 + d] = acc;
}

// ---------------------------------------------------------------------------
// Kernel 3: vself[u][d] = sum_j M1t[j][d] * self_x[u][j]   (one block per user)
// ---------------------------------------------------------------------------
__global__ void vself_kernel(const float* __restrict__ self_x) {
    int u = blockIdx.x, d = threadIdx.x;
    __shared__ float sx[64];
    sx[d] = self_x[u * 64 + d];
    __syncthreads();
    float acc = 0.f;
#pragma unroll 8
    for (int j = 0; j < 64; j++)
        acc = fmaf(g_M1t[j * 64 + d], sx[j], acc);
    g_vself[u * 64 + d] = acc;
}

// ---------------------------------------------------------------------------
// Kernel 4: v[e][d] = vself[u(e)][d] + sum_j M2t[j][d] * friend_x[e][j]
//           256 threads, 64 edges per block, M2 resident in shared
// ---------------------------------------------------------------------------
__global__ void vedge_kernel(const float* __restrict__ friend_x) {
    __shared__ float M2sh[64 * 64];
    __shared__ float fx[4][64];
    int t = threadIdx.x;          // 256
    for (int i = t; i < 4096; i += 256) M2sh[i] = g_M2t[i];
    int es = t >> 6, d = t & 63;
    int ebase = blockIdx.x * 64;
#pragma unroll 1
    for (int g = 0; g < 16; g++) {
        int e = ebase + g * 4 + es;
        __syncthreads();
        fx[es][d] = friend_x[(size_t)e * 64 + d];
        __syncthreads();
        int u = g_edge_user[e];
        float acc = g_vself[u * 64 + d];
#pragma unroll 8
        for (int j = 0; j < 64; j++)
            acc = fmaf(M2sh[j * 64 + d], fx[es][j], acc);
        g_v[(size_t)e * 64 + d] = acc;
    }
}

// ---------------------------------------------------------------------------
// Kernel 5 (main, HBM-bound): per edge, stream 16KB common_x tile,
// score = common_x[e,c,:]·v[e], softplus * temporal * mask, reduce over c.
// ---------------------------------------------------------------------------
__global__ __launch_bounds__(64, 32)
void main_kernel(const float* __restrict__ common_x,
                 const float* __restrict__ common_time,
                 const int*   __restrict__ common_src_mask,
                 float* __restrict__ out, int max_n, long long out_elems) {
    int e = blockIdx.x;
    int c = threadIdx.x;    // 0..63
    __shared__ float vsh[64];
    __shared__ int   s_u;
    __shared__ long long s_off;
    __shared__ float part[2];

    vsh[c] = g_v[(size_t)e * 64 + c];
    if (c == 0) {
        int u = g_edge_user[e];
        s_u = u;
        s_off = g_offsets[u];
    }
    __syncthreads();

    const float4* row = (const float4*)(common_x + ((size_t)e * 64 + c) * 64);
    const float4* v4  = (const float4*)vsh;

    float a0 = 0.f, a1 = 0.f, a2 = 0.f, a3 = 0.f;
#pragma unroll
    for (int i = 0; i < 16; i += 4) {
        float4 x0 = row[i + 0], x1 = row[i + 1], x2 = row[i + 2], x3 = row[i + 3];
        float4 w0 = v4[i + 0],  w1 = v4[i + 1],  w2 = v4[i + 2],  w3 = v4[i + 3];
        a0 = fmaf(x0.x, w0.x, fmaf(x0.y, w0.y, fmaf(x0.z, w0.z, fmaf(x0.w, w0.w, a0))));
        a1 = fmaf(x1.x, w1.x, fmaf(x1.y, w1.y, fmaf(x1.z, w1.z, fmaf(x1.w, w1.w, a1))));
        a2 = fmaf(x2.x, w2.x, fmaf(x2.y, w2.y, fmaf(x2.z, w2.z, fmaf(x2.w, w2.w, a2))));
        a3 = fmaf(x3.x, w3.x, fmaf(x3.y, w3.y, fmaf(x3.z, w3.z, fmaf(x3.w, w3.w, a3))));
    }
    float score = (a0 + a1) + (a2 + a3);

    float tm = common_time[(size_t)e * 64 + c];
    float mk = (float)common_src_mask[(size_t)e * 64 + c];

    // stable softplus
    float sp = fmaxf(score, 0.f) + log1pf(expf(-fabsf(score)));
    float w = sp * expf(fmaf(tm, -1e-6f, 1.0f)) * mk;

    // reduce over 64 threads
#pragma unroll
    for (int o = 16; o > 0; o >>= 1)
        w += __shfl_down_sync(0xffffffffu, w, o);
    if ((c & 31) == 0) part[c >> 5] = w;
    __syncthreads();
    if (c == 0) {
        long long oi = (long long)s_u * max_n + (long long)(e - s_off);
        if (oi >= 0 && oi < out_elems)
            out[oi] = part[0] + part[1];
    }
}

// ---------------------------------------------------------------------------
extern "C" void kernel_launch(void* const* d_in, const int* in_sizes, int n_in,
                              void* d_out, int out_size) {
    const float* self_x      = (const float*)d_in[0];
    const float* common_x    = (const float*)d_in[1];
    const float* common_time = (const float*)d_in[2];
    const int*   src_mask    = (const int*)d_in[3];
    const float* friend_x    = (const float*)d_in[4];
    const void*  counts      = (const void*)d_in[5];
    const float* W_friend    = (const float*)d_in[6];
    const float* W_beta      = (const float*)d_in[7];
    float*       out         = (float*)d_out;

    int B = in_sizes[5];
    int E = in_sizes[4] / 64;
    int max_n = out_size / B;

    setup_kernel<<<1, BMAX>>>(counts, B, E);
    mfold_kernel<<<(2 * DD * DD + 255) / 256, 256>>>(W_friend, W_beta);
    vself_kernel<<<B, 64>>>(self_x);
    vedge_kernel<<<E / 64, 256>>>(friend_x);
    cudaMemsetAsync(d_out, 0, (size_t)out_size * sizeof(float), 0);
    main_kernel<<<E, 64>>>(common_x, common_time, src_mask, out, max_n,
                           (long long)out_size);
}

// round 7
// speedup vs baseline: 1.4877x; 1.4877x over previous
#include <cuda_runtime.h>
#include <cuda_bf16.h>
#include <math.h>

// Problem constants (fixed by the dataset)
#define BMAX 1024
#define EMAX 32768
#define CC   64
#define DD   64

// Scratch (static device globals — no allocation allowed)
__device__ long long g_offsets[BMAX + 1];
__device__ int       g_edge_user[EMAX];
__device__ float     g_M1t[DD * DD];     // [j][d] : self part of Wb^T Wf
__device__ float     g_M2t[DD * DD];     // [j][d] : friend part
__device__ float     g_vself[BMAX * DD];
__device__ float     g_v[(size_t)EMAX * DD];

// ---------------------------------------------------------------------------
// Kernel 1: dtype-robust prefix-scan of counts, fill edge->user map.
// ---------------------------------------------------------------------------
__global__ void setup_kernel(const void* __restrict__ counts_raw, int B, int E) {
    __shared__ long long s[BMAX];
    __shared__ int use64;
    int t = threadIdx.x;

    const long long* c64 = (const long long*)counts_raw;
    const int*       c32 = (const int*)counts_raw;

    long long v64 = (t < B) ? c64[t] : 0;
    s[t] = v64;
    __syncthreads();
    for (int o = BMAX >> 1; o > 0; o >>= 1) {
        if (t < o) s[t] += s[t + o];
        __syncthreads();
    }
    if (t == 0) use64 = (s[0] == (long long)E) ? 1 : 0;
    __syncthreads();
    int u64 = use64;
    __syncthreads();

    long long c = 0;
    if (t < B) c = u64 ? c64[t] : (long long)c32[t];
    if (c < 0) c = 0;
    if (c > (long long)EMAX) c = EMAX;

    s[t] = c;
    __syncthreads();
    for (int o = 1; o < BMAX; o <<= 1) {
        long long add = (t >= o) ? s[t - o] : 0;
        __syncthreads();
        s[t] += add;
        __syncthreads();
    }
    if (t == 0) g_offsets[0] = 0;
    if (t < B) g_offsets[t + 1] = s[t];
    long long off = s[t] - c;
    if (t < B) {
        for (long long i = 0; i < c; i++) {
            long long idx = off + i;
            if (idx >= 0 && idx < (long long)EMAX) g_edge_user[idx] = t;
        }
    }
}

// ---------------------------------------------------------------------------
// Kernel 2: M1t[j][d] = sum_f Wb[f][d] * Wf[f][j]
//           M2t[j][d] = sum_f Wb[f][d] * Wf[f][64+j]
// ---------------------------------------------------------------------------
__global__ void mfold_kernel(const float* __restrict__ Wf,
                             const float* __restrict__ Wb) {
    int idx = blockIdx.x * blockDim.x + threadIdx.x;
    if (idx >= 2 * DD * DD) return;
    int d = idx & 63;
    int j = (idx >> 6) & 63;
    int which = idx >> 12;
    float acc = 0.f;
#pragma unroll 8
    for (int f = 0; f < 64; f++)
        acc = fmaf(Wb[f * 64 + d], Wf[f * 128 + which * 64 + j], acc);
    if (which) g_M2t[j * 64 + d] = acc;
    else       g_M1t[j * 64 + d] = acc;
}

// ---------------------------------------------------------------------------
// Kernel 3: vself[u][d] = sum_j M1t[j][d] * self_x[u][j]
// ---------------------------------------------------------------------------
__global__ void vself_kernel(const float* __restrict__ self_x) {
    int u = blockIdx.x, d = threadIdx.x;
    __shared__ float sx[64];
    sx[d] = self_x[u * 64 + d];
    __syncthreads();
    float acc = 0.f;
#pragma unroll 8
    for (int j = 0; j < 64; j++)
        acc = fmaf(g_M1t[j * 64 + d], sx[j], acc);
    g_vself[u * 64 + d] = acc;
}

// ---------------------------------------------------------------------------
// Kernel 4 (v2): v[e][d] = vself[u(e)][d] + sum_j M2t[j][d] * friend_x[e][j]
// Register-tiled: 256 threads, M2 in shared ONCE per block as float4,
// each thread computes a float4 of v for 2 edges -> 3 LDS per 8 FMA.
// grid = E/128; each block processes 128 edges in 4 groups of 32.
// ---------------------------------------------------------------------------
#define FXPAD 68
__global__ __launch_bounds__(256) void vedge_kernel(const float* __restrict__ fx_g) {
    __shared__ float4 M2sh[64 * 16];          // [j][q], 16 KB
    __shared__ float  fxs[32 * FXPAD];        // 32 edges, padded rows (8.5 KB)
    int t = threadIdx.x;

    const float4* M2g = (const float4*)g_M2t;
    for (int i = t; i < 1024; i += 256) M2sh[i] = M2g[i];

    int q = t & 15;      // which float4 of d (0..15)
    int r = t >> 4;      // 0..15, handles edges 2r and 2r+1 of the group
    int ebase = blockIdx.x * 128;

    for (int it = 0; it < 4; it++) {
        int e0 = ebase + it * 32;
        __syncthreads();
        // stage fx for 32 edges (512 float4 loads by 256 threads)
        for (int i = t; i < 512; i += 256) {
            int ee = i >> 4, qq = i & 15;
            float4 f = ((const float4*)(fx_g + (size_t)(e0 + ee) * 64))[qq];
            *((float4*)(fxs + ee * FXPAD + qq * 4)) = f;
        }
        __syncthreads();

        int ea = e0 + 2 * r, eb = ea + 1;
        int ua = g_edge_user[ea], ub = g_edge_user[eb];
        float4 acc0 = ((const float4*)(g_vself + (size_t)ua * 64))[q];
        float4 acc1 = ((const float4*)(g_vself + (size_t)ub * 64))[q];
        const float* fa = fxs + (2 * r) * FXPAD;
        const float* fb = fxs + (2 * r + 1) * FXPAD;
#pragma unroll 16
        for (int j = 0; j < 64; j++) {
            float4 m = M2sh[j * 16 + q];
            float a = fa[j], b = fb[j];
            acc0.x = fmaf(m.x, a, acc0.x);
            acc0.y = fmaf(m.y, a, acc0.y);
            acc0.z = fmaf(m.z, a, acc0.z);
            acc0.w = fmaf(m.w, a, acc0.w);
            acc1.x = fmaf(m.x, b, acc1.x);
            acc1.y = fmaf(m.y, b, acc1.y);
            acc1.z = fmaf(m.z, b, acc1.z);
            acc1.w = fmaf(m.w, b, acc1.w);
        }
        ((float4*)(g_v + (size_t)ea * 64))[q] = acc0;
        ((float4*)(g_v + (size_t)eb * 64))[q] = acc1;
    }
}

// ---------------------------------------------------------------------------
// Kernel 5 (main, HBM-bound): per edge, stream the common_x tile,
// SKIPPING rows whose mask is 0 (saves ~50% of DRAM traffic).
// ---------------------------------------------------------------------------
__global__ __launch_bounds__(64, 32)
void main_kernel(const float* __restrict__ common_x,
                 const float* __restrict__ common_time,
                 const int*   __restrict__ common_src_mask,
                 float* __restrict__ out, int max_n, long long out_elems) {
    int e = blockIdx.x;
    int c = threadIdx.x;    // 0..63  (one row of the [64,64] tile per thread)
    __shared__ float vsh[64];
    __shared__ int   s_u;
    __shared__ long long s_off;
    __shared__ float part[2];

    vsh[c] = g_v[(size_t)e * 64 + c];
    if (c == 0) {
        int u = g_edge_user[e];
        s_u = u;
        s_off = g_offsets[u];
    }

    // mask/time first: if the row is masked out we never touch its 256 B
    int   mk = common_src_mask[(size_t)e * 64 + c];
    float tm = common_time[(size_t)e * 64 + c];
    __syncthreads();

    float w = 0.f;
    if (mk != 0) {
        const float4* row = (const float4*)(common_x + ((size_t)e * 64 + c) * 64);
        const float4* v4  = (const float4*)vsh;
        float a0 = 0.f, a1 = 0.f, a2 = 0.f, a3 = 0.f;
#pragma unroll
        for (int i = 0; i < 16; i += 4) {
            float4 x0 = row[i + 0], x1 = row[i + 1], x2 = row[i + 2], x3 = row[i + 3];
            float4 w0 = v4[i + 0],  w1 = v4[i + 1],  w2 = v4[i + 2],  w3 = v4[i + 3];
            a0 = fmaf(x0.x, w0.x, fmaf(x0.y, w0.y, fmaf(x0.z, w0.z, fmaf(x0.w, w0.w, a0))));
            a1 = fmaf(x1.x, w1.x, fmaf(x1.y, w1.y, fmaf(x1.z, w1.z, fmaf(x1.w, w1.w, a1))));
            a2 = fmaf(x2.x, w2.x, fmaf(x2.y, w2.y, fmaf(x2.z, w2.z, fmaf(x2.w, w2.w, a2))));
            a3 = fmaf(x3.x, w3.x, fmaf(x3.y, w3.y, fmaf(x3.z, w3.z, fmaf(x3.w, w3.w, a3))));
        }
        float score = (a0 + a1) + (a2 + a3);
        // stable softplus
        float sp = fmaxf(score, 0.f) + log1pf(expf(-fabsf(score)));
        w = sp * expf(fmaf(tm, -1e-6f, 1.0f));
    }

    // reduce over 64 threads
#pragma unroll
    for (int o = 16; o > 0; o >>= 1)
        w += __shfl_down_sync(0xffffffffu, w, o);
    if ((c & 31) == 0) part[c >> 5] = w;
    __syncthreads();
    if (c == 0) {
        long long oi = (long long)s_u * max_n + (long long)(e - s_off);
        if (oi >= 0 && oi < out_elems)
            out[oi] = part[0] + part[1];
    }
}

// ---------------------------------------------------------------------------
extern "C" void kernel_launch(void* const* d_in, const int* in_sizes, int n_in,
                              void* d_out, int out_size) {
    const float* self_x      = (const float*)d_in[0];
    const float* common_x    = (const float*)d_in[1];
    const float* common_time = (const float*)d_in[2];
    const int*   src_mask    = (const int*)d_in[3];
    const float* friend_x    = (const float*)d_in[4];
    const void*  counts      = (const void*)d_in[5];
    const float* W_friend    = (const float*)d_in[6];
    const float* W_beta      = (const float*)d_in[7];
    float*       out         = (float*)d_out;

    int B = in_sizes[5];
    int E = in_sizes[4] / 64;
    int max_n = out_size / B;

    setup_kernel<<<1, BMAX>>>(counts, B, E);
    mfold_kernel<<<(2 * DD * DD + 255) / 256, 256>>>(W_friend, W_beta);
    vself_kernel<<<B, 64>>>(self_x);
    vedge_kernel<<<E / 128, 256>>>(friend_x);
    cudaMemsetAsync(d_out, 0, (size_t)out_size * sizeof(float), 0);
    main_kernel<<<E, 64>>>(common_x, common_time, src_mask, out, max_n,
                           (long long)out_size);
}

// round 8
// speedup vs baseline: 1.6005x; 1.0758x over previous
#include <cuda_runtime.h>
#include <cuda_bf16.h>
#include <math.h>

// Problem constants (fixed by the dataset)
#define BMAX 1024
#define EMAX 32768
#define CC   64
#define DD   64

// Scratch (static device globals — no allocation allowed)
__device__ long long g_offsets[BMAX + 1];
__device__ int       g_edge_user[EMAX];
__device__ float     g_M1t[DD * DD];     // [j][d] : self part of Wb^T Wf
__device__ float     g_M2t[DD * DD];     // [j][d] : friend part
__device__ float     g_vself[BMAX * DD];
__device__ float     g_v[(size_t)EMAX * DD];

// ---------------------------------------------------------------------------
// Kernel 1: dtype-robust prefix-scan of counts, fill edge->user map.
// ---------------------------------------------------------------------------
__global__ void setup_kernel(const void* __restrict__ counts_raw, int B, int E) {
    __shared__ long long s[BMAX];
    __shared__ int use64;
    int t = threadIdx.x;

    const long long* c64 = (const long long*)counts_raw;
    const int*       c32 = (const int*)counts_raw;

    long long v64 = (t < B) ? c64[t] : 0;
    s[t] = v64;
    __syncthreads();
    for (int o = BMAX >> 1; o > 0; o >>= 1) {
        if (t < o) s[t] += s[t + o];
        __syncthreads();
    }
    if (t == 0) use64 = (s[0] == (long long)E) ? 1 : 0;
    __syncthreads();
    int u64 = use64;
    __syncthreads();

    long long c = 0;
    if (t < B) c = u64 ? c64[t] : (long long)c32[t];
    if (c < 0) c = 0;
    if (c > (long long)EMAX) c = EMAX;

    s[t] = c;
    __syncthreads();
    for (int o = 1; o < BMAX; o <<= 1) {
        long long add = (t >= o) ? s[t - o] : 0;
        __syncthreads();
        s[t] += add;
        __syncthreads();
    }
    if (t == 0) g_offsets[0] = 0;
    if (t < B) g_offsets[t + 1] = s[t];
    long long off = s[t] - c;
    if (t < B) {
        for (long long i = 0; i < c; i++) {
            long long idx = off + i;
            if (idx >= 0 && idx < (long long)EMAX) g_edge_user[idx] = t;
        }
    }
}

// ---------------------------------------------------------------------------
// Kernel 2: M1t[j][d] = sum_f Wb[f][d] * Wf[f][j]
//           M2t[j][d] = sum_f Wb[f][d] * Wf[f][64+j]
// ---------------------------------------------------------------------------
__global__ void mfold_kernel(const float* __restrict__ Wf,
                             const float* __restrict__ Wb) {
    int idx = blockIdx.x * blockDim.x + threadIdx.x;
    if (idx >= 2 * DD * DD) return;
    int d = idx & 63;
    int j = (idx >> 6) & 63;
    int which = idx >> 12;
    float acc = 0.f;
#pragma unroll 8
    for (int f = 0; f < 64; f++)
        acc = fmaf(Wb[f * 64 + d], Wf[f * 128 + which * 64 + j], acc);
    if (which) g_M2t[j * 64 + d] = acc;
    else       g_M1t[j * 64 + d] = acc;
}

// ---------------------------------------------------------------------------
// Kernel 3: vself[u][d] = sum_j M1t[j][d] * self_x[u][j]
// ---------------------------------------------------------------------------
__global__ void vself_kernel(const float* __restrict__ self_x) {
    int u = blockIdx.x, d = threadIdx.x;
    __shared__ float sx[64];
    sx[d] = self_x[u * 64 + d];
    __syncthreads();
    float acc = 0.f;
#pragma unroll 8
    for (int j = 0; j < 64; j++)
        acc = fmaf(g_M1t[j * 64 + d], sx[j], acc);
    g_vself[u * 64 + d] = acc;
}

// ---------------------------------------------------------------------------
// Kernel 4 (v3): v[e][d] = vself[u(e)][d] + sum_j M2t[j][d] * friend_x[e][j]
// Register-tiled, 32 edges per block, grid = E/32 = 1024 for occupancy.
// Each thread computes a float4 of v for 2 edges -> 3 LDS per 8 FMA.
// ---------------------------------------------------------------------------
#define FXPAD 68
__global__ __launch_bounds__(256) void vedge_kernel(const float* __restrict__ fx_g) {
    __shared__ float4 M2sh[64 * 16];          // [j][q], 16 KB
    __shared__ float  fxs[32 * FXPAD];        // 32 edges, padded rows (8.5 KB)
    int t = threadIdx.x;

    const float4* M2g = (const float4*)g_M2t;
    for (int i = t; i < 1024; i += 256) M2sh[i] = M2g[i];

    int e0 = blockIdx.x * 32;
    // stage fx for 32 edges (512 float4 loads by 256 threads)
    for (int i = t; i < 512; i += 256) {
        int ee = i >> 4, qq = i & 15;
        float4 f = ((const float4*)(fx_g + (size_t)(e0 + ee) * 64))[qq];
        *((float4*)(fxs + ee * FXPAD + qq * 4)) = f;
    }
    __syncthreads();

    int q = t & 15;      // which float4 of d (0..15)
    int r = t >> 4;      // 0..15, handles edges 2r and 2r+1
    int ea = e0 + 2 * r, eb = ea + 1;
    int ua = g_edge_user[ea], ub = g_edge_user[eb];
    float4 acc0 = ((const float4*)(g_vself + (size_t)ua * 64))[q];
    float4 acc1 = ((const float4*)(g_vself + (size_t)ub * 64))[q];
    const float* fa = fxs + (2 * r) * FXPAD;
    const float* fb = fxs + (2 * r + 1) * FXPAD;
#pragma unroll 16
    for (int j = 0; j < 64; j++) {
        float4 m = M2sh[j * 16 + q];
        float a = fa[j], b = fb[j];
        acc0.x = fmaf(m.x, a, acc0.x);
        acc0.y = fmaf(m.y, a, acc0.y);
        acc0.z = fmaf(m.z, a, acc0.z);
        acc0.w = fmaf(m.w, a, acc0.w);
        acc1.x = fmaf(m.x, b, acc1.x);
        acc1.y = fmaf(m.y, b, acc1.y);
        acc1.z = fmaf(m.z, b, acc1.z);
        acc1.w = fmaf(m.w, b, acc1.w);
    }
    ((float4*)(g_v + (size_t)ea * 64))[q] = acc0;
    ((float4*)(g_v + (size_t)eb * 64))[q] = acc1;
}

// ---------------------------------------------------------------------------
// Kernel 5 (main, HBM-bound): 4 edges per 256-thread block, one row per
// thread. Mask-gated row skipping (~50% DRAM saved). NO occupancy cap:
// letting regs float avoids the catastrophic spills of launch_bounds(64,32).
// ---------------------------------------------------------------------------
__global__ __launch_bounds__(256)
void main_kernel(const float* __restrict__ common_x,
                 const float* __restrict__ common_time,
                 const int*   __restrict__ common_src_mask,
                 float* __restrict__ out, int max_n, long long out_elems) {
    int g = threadIdx.x >> 6;        // edge slot 0..3 (aligned to warp pairs)
    int c = threadIdx.x & 63;        // row 0..63
    int e = blockIdx.x * 4 + g;

    __shared__ float vsh[4][64];
    __shared__ float part[4][2];

    vsh[g][c] = g_v[(size_t)e * 64 + c];

    // mask/time first: masked-out rows never touch their 256 B of common_x
    int   mk = common_src_mask[(size_t)e * 64 + c];
    float tm = common_time[(size_t)e * 64 + c];
    __syncthreads();

    float w = 0.f;
    if (mk != 0) {
        const float4* row = (const float4*)(common_x + ((size_t)e * 64 + c) * 64);
        const float4* v4  = (const float4*)vsh[g];
        float a0 = 0.f, a1 = 0.f, a2 = 0.f, a3 = 0.f;
#pragma unroll
        for (int i = 0; i < 16; i += 4) {
            float4 x0 = row[i + 0], x1 = row[i + 1], x2 = row[i + 2], x3 = row[i + 3];
            float4 w0 = v4[i + 0],  w1 = v4[i + 1],  w2 = v4[i + 2],  w3 = v4[i + 3];
            a0 = fmaf(x0.x, w0.x, fmaf(x0.y, w0.y, fmaf(x0.z, w0.z, fmaf(x0.w, w0.w, a0))));
            a1 = fmaf(x1.x, w1.x, fmaf(x1.y, w1.y, fmaf(x1.z, w1.z, fmaf(x1.w, w1.w, a1))));
            a2 = fmaf(x2.x, w2.x, fmaf(x2.y, w2.y, fmaf(x2.z, w2.z, fmaf(x2.w, w2.w, a2))));
            a3 = fmaf(x3.x, w3.x, fmaf(x3.y, w3.y, fmaf(x3.z, w3.z, fmaf(x3.w, w3.w, a3))));
        }
        float score = (a0 + a1) + (a2 + a3);
        // stable softplus
        float sp = fmaxf(score, 0.f) + log1pf(expf(-fabsf(score)));
        w = sp * expf(fmaf(tm, -1e-6f, 1.0f));
    }

    // reduce 64 threads of this edge slot (2 warps)
#pragma unroll
    for (int o = 16; o > 0; o >>= 1)
        w += __shfl_down_sync(0xffffffffu, w, o);
    if ((c & 31) == 0) part[g][c >> 5] = w;
    __syncthreads();
    if (c == 0) {
        int u = g_edge_user[e];
        long long oi = (long long)u * max_n + (long long)(e - g_offsets[u]);
        if (oi >= 0 && oi < out_elems)
            out[oi] = part[g][0] + part[g][1];
    }
}

// ---------------------------------------------------------------------------
extern "C" void kernel_launch(void* const* d_in, const int* in_sizes, int n_in,
                              void* d_out, int out_size) {
    const float* self_x      = (const float*)d_in[0];
    const float* common_x    = (const float*)d_in[1];
    const float* common_time = (const float*)d_in[2];
    const int*   src_mask    = (const int*)d_in[3];
    const float* friend_x    = (const float*)d_in[4];
    const void*  counts      = (const void*)d_in[5];
    const float* W_friend    = (const float*)d_in[6];
    const float* W_beta      = (const float*)d_in[7];
    float*       out         = (float*)d_out;

    int B = in_sizes[5];
    int E = in_sizes[4] / 64;
    int max_n = out_size / B;

    setup_kernel<<<1, BMAX>>>(counts, B, E);
    mfold_kernel<<<(2 * DD * DD + 255) / 256, 256>>>(W_friend, W_beta);
    vself_kernel<<<B, 64>>>(self_x);
    vedge_kernel<<<E / 32, 256>>>(friend_x);
    cudaMemsetAsync(d_out, 0, (size_t)out_size * sizeof(float), 0);
    main_kernel<<<E / 4, 256>>>(common_x, common_time, src_mask, out, max_n,
                                (long long)out_size);
}